// round 8
// baseline (speedup 1.0000x reference)
#include <cuda_runtime.h>
#include <cuda_bf16.h>

#define N_ROWS 256
#define D_COLS 8192
#define LAMBDA 0.005f
#define SPLITS 24
#define NTILES 3              // symmetric 128x128 tile pairs: (0,0),(0,1),(1,1)
#define TILE_ELEMS 16384
#define BK 64                 // k per mainloop iter == stats slab width
#define LDB 72                // smem row stride in bf16 (144 B, 9 granules -> conflict-free)
#define TILE_BUF 18432        // 128 * 144 bytes
#define DYN_SMEM 73728        // 2 sides * 2 buffers * TILE_BUF
#define NBLK 148
#define NTHR 1024
#define CROSS_TASKS 12288     // 3*TILE_ELEMS/4 float4 tasks
#define TPB_CROSS 84          // ceil(12288/148)

// ---- scratch ----
__device__ __align__(16) __nv_bfloat16 g_Zn[2][N_ROWS * D_COLS];      // normalized bf16, 8 MB
__device__ float g_diag[128];
__device__ __align__(16) float g_GP[2][SPLITS][NTILES * TILE_ELEMS];  // 9.4 MB partials
__device__ float g_red[NBLK];
__device__ unsigned g_flag[128];    // per-k-chunk ready flags (reset in-kernel)
__device__ unsigned g_bar_count;
__device__ unsigned g_bar_gen;
__device__ unsigned g_fin;

// ---------------------------------------------------------------------------
__device__ __forceinline__ void grid_sync() {
    __syncthreads();
    if (threadIdx.x == 0) {
        __threadfence();
        const unsigned gen = *(volatile unsigned*)&g_bar_gen;
        if (atomicAdd(&g_bar_count, 1u) == NBLK - 1) {
            g_bar_count = 0;
            __threadfence();
            *(volatile unsigned*)&g_bar_gen = gen + 1;
        } else {
            while (*(volatile unsigned*)&g_bar_gen == gen) {}
        }
        __threadfence();
    }
    __syncthreads();
}

__device__ __forceinline__ void mma_bf16(float* c, const unsigned* a, unsigned b0, unsigned b1) {
    asm volatile(
        "mma.sync.aligned.m16n8k16.row.col.f32.bf16.bf16.f32 "
        "{%0,%1,%2,%3}, {%4,%5,%6,%7}, {%8,%9}, {%0,%1,%2,%3};\n"
        : "+f"(c[0]), "+f"(c[1]), "+f"(c[2]), "+f"(c[3])
        : "r"(a[0]), "r"(a[1]), "r"(a[2]), "r"(a[3]), "r"(b0), "r"(b1));
}
__device__ __forceinline__ void ldm4(unsigned* r, unsigned addr) {
    asm volatile("ldmatrix.sync.aligned.m8n8.x4.shared.b16 {%0,%1,%2,%3}, [%4];\n"
        : "=r"(r[0]), "=r"(r[1]), "=r"(r[2]), "=r"(r[3]) : "r"(addr));
}
__device__ __forceinline__ void cp_async16(unsigned dst, const void* src) {
    asm volatile("cp.async.cg.shared.global [%0], [%1], 16;\n" :: "r"(dst), "l"(src));
}

// wait (whole block) until k-chunk `ch` of g_Zn is published
__device__ __forceinline__ void chunk_wait(int ch) {
    if (threadIdx.x == 0) {
        while (*(volatile unsigned*)&g_flag[ch] == 0u) { __nanosleep(64); }
        __threadfence();
    }
    __syncthreads();
}

__global__ __launch_bounds__(NTHR, 1)
void fused_kernel(const float* __restrict__ za, const float* __restrict__ zb,
                  float* __restrict__ out) {
    extern __shared__ __align__(16) unsigned char dyn[];
    __shared__ float s_red[NTHR];
    __shared__ unsigned s_last;

    const int bid = blockIdx.x;
    const int tid = threadIdx.x;

    // ========== Phase 0 (bid<128): single-pass stats + normalize + diag =====
    if (bid < 128) {
        float (*s_st)[64 * 5] = (float (*)[64 * 5])dyn;                   // [16][320]
        float* s_mu = (float*)(dyn + 20480);                               // [2][64]
        float* s_inv = (float*)(dyn + 20480 + 512);                        // [2][64]

        const int c = tid & 63;
        const int gq = tid >> 6;          // 0..15, 16 rows each
        const int col = bid * 64 + c;
        const float* __restrict__ pa = za + (size_t)(gq * 16) * D_COLS + col;
        const float* __restrict__ pb = zb + (size_t)(gq * 16) * D_COLS + col;

        float va[16], vb[16];
        float sa = 0.f, sb = 0.f, saa = 0.f, sbb = 0.f, sab = 0.f;
#pragma unroll
        for (int n = 0; n < 16; ++n) {
            va[n] = pa[n * D_COLS];
            vb[n] = pb[n * D_COLS];
        }
#pragma unroll
        for (int n = 0; n < 16; ++n) {
            sa += va[n]; sb += vb[n];
            saa += va[n] * va[n]; sbb += vb[n] * vb[n]; sab += va[n] * vb[n];
        }
        s_st[gq][c * 5 + 0] = sa;
        s_st[gq][c * 5 + 1] = sb;
        s_st[gq][c * 5 + 2] = saa;
        s_st[gq][c * 5 + 3] = sbb;
        s_st[gq][c * 5 + 4] = sab;
        __syncthreads();

        float term = 0.f;
        if (tid < 64) {
            float t0 = 0.f, t1 = 0.f, t2 = 0.f, t3 = 0.f, t4 = 0.f;
#pragma unroll
            for (int g = 0; g < 16; ++g) {
                t0 += s_st[g][tid * 5 + 0];
                t1 += s_st[g][tid * 5 + 1];
                t2 += s_st[g][tid * 5 + 2];
                t3 += s_st[g][tid * 5 + 3];
                t4 += s_st[g][tid * 5 + 4];
            }
            const float mua = t0 * (1.f / 256.f);
            const float mub = t1 * (1.f / 256.f);
            const float ia = rsqrtf((t2 - t0 * mua) * (1.f / 255.f));
            const float ib = rsqrtf((t3 - t1 * mub) * (1.f / 255.f));
            const float cdd = (t4 - 256.f * mua * mub) * ia * ib * (1.f / 256.f);
            term = (cdd - 1.f) * (cdd - 1.f) - LAMBDA * cdd * cdd;
            s_mu[tid] = mua; s_mu[64 + tid] = mub;
            s_inv[tid] = ia; s_inv[64 + tid] = ib;
        }
        s_red[tid] = term;
        __syncthreads();
#pragma unroll
        for (int off = 32; off > 0; off >>= 1) {   // data only in tids 0..63
            if (tid < off) s_red[tid] += s_red[tid + off];
            __syncthreads();
        }
        if (tid == 0) g_diag[bid] = s_red[0];

        // normalize from registers, write bf16
        const float ma = s_mu[c],      wa = s_inv[c];
        const float mb = s_mu[64 + c], wb = s_inv[64 + c];
        __nv_bfloat16* __restrict__ oa = g_Zn[0] + (size_t)(gq * 16) * D_COLS + col;
        __nv_bfloat16* __restrict__ ob = g_Zn[1] + (size_t)(gq * 16) * D_COLS + col;
#pragma unroll
        for (int n = 0; n < 16; ++n) {
            oa[n * D_COLS] = __float2bfloat16_rn((va[n] - ma) * wa);
            ob[n * D_COLS] = __float2bfloat16_rn((vb[n] - mb) * wb);
        }

        // publish this k-chunk
        __threadfence();
        __syncthreads();
        if (tid == 0) *(volatile unsigned*)&g_flag[bid] = 1u;
    }

    // ========== Phase 1 (bid<144): gram, gated per-chunk by flags ===========
    if (bid < 2 * NTILES * SPLITS) {
        const int sel = bid / (NTILES * SPLITS);
        const int rem = bid % (NTILES * SPLITS);
        const int pair = rem / SPLITS;
        const int s = rem % SPLITS;
        const bool dup = (pair != 1);      // diagonal tile pairs: B tile == A tile

        const int m0 = (pair == 2) ? 128 : 0;
        const int n0 = (pair == 0) ? 0 : 128;
        // 128 k-chunks of 64: splits 0..15 get 5, 16..23 get 6
        const int ks = (s < 16) ? s * 5 : 80 + (s - 16) * 6;
        const int kn = (s < 16) ? 5 : 6;

        const __nv_bfloat16* __restrict__ gA = g_Zn[sel] + (size_t)m0 * D_COLS;
        const __nv_bfloat16* __restrict__ gB = g_Zn[sel] + (size_t)n0 * D_COLS;

        const int warp = tid >> 5;
        const int lane = tid & 31;
        const int wm = warp & 7;    // 8 m-strips of 16
        const int wn = warp >> 3;   // 4 n-strips of 32

        float acc[4][4];
#pragma unroll
        for (int j = 0; j < 4; ++j)
#pragma unroll
            for (int k = 0; k < 4; ++k) acc[j][k] = 0.f;

        const unsigned sBase = (unsigned)__cvta_generic_to_shared(dyn);
        const unsigned bRegion = dup ? sBase : (sBase + 2u * TILE_BUF);
        const int laR = (lane & 7) + (lane & 8);
        const int laC = (lane >> 1) & 8;
        const int lbR = (lane & 7) + ((lane >> 1) & 8);
        const int lbC = (lane & 8);
        const unsigned aAddr = sBase + (unsigned)(((wm * 16 + laR) * LDB + laC) * 2);
        const unsigned bAddr = bRegion + (unsigned)(((wn * 32 + lbR) * LDB + lbC) * 2);

#define STAGE(bufv, k0v)                                                          \
        {                                                                         \
            const int k0_ = (k0v);                                                \
            const unsigned bo_ = (unsigned)(bufv) * TILE_BUF;                     \
            const int r_ = (tid >> 3) & 127;                                      \
            const int c_ = tid & 7;                                               \
            cp_async16(sBase + bo_ + (unsigned)(r_ * 144 + c_ * 16),              \
                       gA + (size_t)r_ * D_COLS + k0_ + c_ * 8);                  \
            if (!dup)                                                             \
                cp_async16(sBase + 2u * TILE_BUF + bo_ + (unsigned)(r_ * 144 + c_ * 16), \
                           gB + (size_t)r_ * D_COLS + k0_ + c_ * 8);              \
            asm volatile("cp.async.commit_group;\n");                             \
        }

        chunk_wait(ks);
        STAGE(0, ks * BK);
        int buf = 0;
        for (int it = 0; it < kn; ++it) {
            if (it + 1 < kn) {
                chunk_wait(ks + it + 1);
                STAGE(buf ^ 1, (ks + it + 1) * BK);
                asm volatile("cp.async.wait_group 1;\n");
            } else {
                asm volatile("cp.async.wait_group 0;\n");
            }
            __syncthreads();

            const unsigned off = (unsigned)buf * TILE_BUF;
#pragma unroll
            for (int kf = 0; kf < 4; ++kf) {
                unsigned A[4];
                ldm4(A, aAddr + off + (unsigned)(kf * 32));
#pragma unroll
                for (int fp = 0; fp < 2; ++fp) {
                    unsigned B[4];
                    ldm4(B, bAddr + off + (unsigned)(fp * 16 * 144 + kf * 32));
                    mma_bf16(acc[2 * fp],     A, B[0], B[1]);
                    mma_bf16(acc[2 * fp + 1], A, B[2], B[3]);
                }
            }
            __syncthreads();
            buf ^= 1;
        }
#undef STAGE

        float* __restrict__ outp = &g_GP[sel][s][pair * TILE_ELEMS];
#pragma unroll
        for (int fn = 0; fn < 4; ++fn) {
            const int i = wm * 16 + (lane >> 2);
            const int j = wn * 32 + fn * 8 + (lane & 3) * 2;
            float2 lo = {acc[fn][0], acc[fn][1]};
            float2 hi = {acc[fn][2], acc[fn][3]};
            *(float2*)&outp[i * 128 + j] = lo;
            *(float2*)&outp[(i + 8) * 128 + j] = hi;
        }
    }

    grid_sync();

    // reset flags for next graph replay (no reader of flags after this point)
    if (bid < 128 && tid == 0) g_flag[bid] = 0u;

    // ========== Phase 2: cross reduction over all 148 blocks + fused final ==
    {
        float v = 0.f;
        const int t = bid * TPB_CROSS + tid;   // 84 contiguous tasks per block
        if (tid < TPB_CROSS && t < CROSS_TASKS) {
            const int pair = t >> 12;
            const float w = (pair == 1) ? 2.f : 1.f;
            float4 ga = {0.f, 0.f, 0.f, 0.f}, gb = {0.f, 0.f, 0.f, 0.f};
#pragma unroll
            for (int s = 0; s < SPLITS; ++s) {
                const float4 a = *(const float4*)&g_GP[0][s][t * 4];
                const float4 bb = *(const float4*)&g_GP[1][s][t * 4];
                ga.x += a.x; ga.y += a.y; ga.z += a.z; ga.w += a.w;
                gb.x += bb.x; gb.y += bb.y; gb.z += bb.z; gb.w += bb.w;
            }
            v = w * (ga.x * gb.x + ga.y * gb.y + ga.z * gb.z + ga.w * gb.w);
        }
        __syncthreads();
        s_red[tid] = v;
        __syncthreads();
#pragma unroll
        for (int off = 64; off > 0; off >>= 1) {   // data only in tids 0..83 (<128)
            if (tid < off) s_red[tid] += s_red[tid + off];
            __syncthreads();
        }
        if (tid == 0) {
            g_red[bid] = s_red[0];
            __threadfence();
            s_last = (atomicAdd(&g_fin, 1u) == NBLK - 1) ? 1u : 0u;
        }
        __syncthreads();

        if (s_last) {
            __threadfence();
            float v2 = 0.f;
            if (tid < NBLK) v2 = (*(volatile float*)&g_red[tid]) * (LAMBDA / (256.f * 256.f));
            if (tid < 128) v2 += *(volatile float*)&g_diag[tid];
            s_red[tid] = v2;
            __syncthreads();
#pragma unroll
            for (int off = 128; off > 0; off >>= 1) {   // data in tids 0..147 (<256)
                if (tid < off) s_red[tid] += s_red[tid + off];
                __syncthreads();
            }
            if (tid == 0) {
                out[0] = s_red[0];
                g_fin = 0;
            }
        }
    }
}

// ---------------------------------------------------------------------------
extern "C" void kernel_launch(void* const* d_in, const int* in_sizes, int n_in,
                              void* d_out, int out_size) {
    const float* za = (const float*)d_in[0];
    const float* zb = (const float*)d_in[1];
    float* out = (float*)d_out;
    cudaFuncSetAttribute(fused_kernel, cudaFuncAttributeMaxDynamicSharedMemorySize, DYN_SMEM);
    fused_kernel<<<NBLK, NTHR, DYN_SMEM>>>(za, zb, out);
}

// round 10
// speedup vs baseline: 1.2434x; 1.2434x over previous
#include <cuda_runtime.h>
#include <cuda_bf16.h>

#define N_ROWS 256
#define D_COLS 8192
#define LAMBDA 0.005f
#define SPLITS 24
#define NTILES 3              // symmetric 128x128 tile pairs: (0,0),(0,1),(1,1)
#define TILE_ELEMS 16384
#define BK 64                 // k per mainloop iter
#define LDB 72                // smem row stride in bf16 (144 B, odd granule count -> conflict-free)
#define TILE_BUF 18432        // 128 * 144 B, one side one stage
#define NSTAGE 3
#define A_REGION (NSTAGE * TILE_BUF)      // 55296
#define DYN_SMEM (2 * NSTAGE * TILE_BUF)  // 110592
#define NBLK 148
#define NTHR 512
#define CROSS_TASKS 12288     // 3*TILE_ELEMS/4 float4 tasks
#define TPB_CROSS 84          // ceil(12288/148)

// ---- scratch ----
__device__ __align__(16) __nv_bfloat16 g_Zn[2][N_ROWS * D_COLS];      // normalized bf16, 8 MB
__device__ float g_diag[128];
__device__ __align__(16) float g_GP[2][SPLITS][NTILES * TILE_ELEMS];  // 9.4 MB partials
__device__ float g_red[NBLK];
__device__ unsigned g_bar_count;
__device__ unsigned g_bar_gen;
__device__ unsigned g_fin;

// ---------------------------------------------------------------------------
__device__ __forceinline__ void grid_sync() {
    __syncthreads();
    if (threadIdx.x == 0) {
        __threadfence();
        const unsigned gen = *(volatile unsigned*)&g_bar_gen;
        if (atomicAdd(&g_bar_count, 1u) == NBLK - 1) {
            g_bar_count = 0;
            __threadfence();
            *(volatile unsigned*)&g_bar_gen = gen + 1;
        } else {
            while (*(volatile unsigned*)&g_bar_gen == gen) {}
        }
        __threadfence();
    }
    __syncthreads();
}

__device__ __forceinline__ void mma_bf16(float* c, const unsigned* a, unsigned b0, unsigned b1) {
    asm volatile(
        "mma.sync.aligned.m16n8k16.row.col.f32.bf16.bf16.f32 "
        "{%0,%1,%2,%3}, {%4,%5,%6,%7}, {%8,%9}, {%0,%1,%2,%3};\n"
        : "+f"(c[0]), "+f"(c[1]), "+f"(c[2]), "+f"(c[3])
        : "r"(a[0]), "r"(a[1]), "r"(a[2]), "r"(a[3]), "r"(b0), "r"(b1));
}
__device__ __forceinline__ void ldm4(unsigned* r, unsigned addr) {
    asm volatile("ldmatrix.sync.aligned.m8n8.x4.shared.b16 {%0,%1,%2,%3}, [%4];\n"
        : "=r"(r[0]), "=r"(r[1]), "=r"(r[2]), "=r"(r[3]) : "r"(addr));
}
__device__ __forceinline__ void cp_async16(unsigned dst, const void* src) {
    asm volatile("cp.async.cg.shared.global [%0], [%1], 16;\n" :: "r"(dst), "l"(src));
}

__global__ __launch_bounds__(NTHR, 1)
void fused_kernel(const float* __restrict__ za, const float* __restrict__ zb,
                  float* __restrict__ out) {
    extern __shared__ __align__(16) unsigned char dyn[];
    __shared__ float s_red[NTHR];
    __shared__ unsigned s_last;

    const int bid = blockIdx.x;
    const int tid = threadIdx.x;

    // ========== Phase 0 (bid<128): stats + diag + normalize =================
    if (bid < 128) {
        float (*s_st)[64 * 5] = (float (*)[64 * 5])dyn;                   // [8][320]
        float* s_mu = (float*)(dyn + 10240);                               // [2][64]
        float* s_inv = (float*)(dyn + 10240 + 512);                        // [2][64]

        const int c = tid & 63;
        const int gq = tid >> 6;          // 0..7, 32 rows each
        const int col = bid * 64 + c;
        const float* __restrict__ pa = za + (size_t)(gq * 32) * D_COLS + col;
        const float* __restrict__ pb = zb + (size_t)(gq * 32) * D_COLS + col;
        float sa = 0.f, sb = 0.f, saa = 0.f, sbb = 0.f, sab = 0.f;
#pragma unroll 8
        for (int n = 0; n < 32; ++n) {
            float a = pa[n * D_COLS];
            float b = pb[n * D_COLS];
            sa += a; sb += b;
            saa += a * a; sbb += b * b; sab += a * b;
        }
        s_st[gq][c * 5 + 0] = sa;
        s_st[gq][c * 5 + 1] = sb;
        s_st[gq][c * 5 + 2] = saa;
        s_st[gq][c * 5 + 3] = sbb;
        s_st[gq][c * 5 + 4] = sab;
        __syncthreads();

        float term = 0.f;
        if (tid < 64) {
            float t0 = 0.f, t1 = 0.f, t2 = 0.f, t3 = 0.f, t4 = 0.f;
#pragma unroll
            for (int g = 0; g < 8; ++g) {
                t0 += s_st[g][tid * 5 + 0];
                t1 += s_st[g][tid * 5 + 1];
                t2 += s_st[g][tid * 5 + 2];
                t3 += s_st[g][tid * 5 + 3];
                t4 += s_st[g][tid * 5 + 4];
            }
            const float mua = t0 * (1.f / 256.f);
            const float mub = t1 * (1.f / 256.f);
            const float ia = rsqrtf((t2 - t0 * mua) * (1.f / 255.f));
            const float ib = rsqrtf((t3 - t1 * mub) * (1.f / 255.f));
            const float cdd = (t4 - 256.f * mua * mub) * ia * ib * (1.f / 256.f);
            term = (cdd - 1.f) * (cdd - 1.f) - LAMBDA * cdd * cdd;
            s_mu[tid] = mua; s_mu[64 + tid] = mub;
            s_inv[tid] = ia; s_inv[64 + tid] = ib;
        }
        s_red[tid] = term;
        __syncthreads();
#pragma unroll
        for (int off = 32; off > 0; off >>= 1) {   // data only in tids 0..63
            if (tid < off) s_red[tid] += s_red[tid + off];
            __syncthreads();
        }
        if (tid == 0) g_diag[bid] = s_red[0];

        // normalize slab -> bf16 (L2-hot re-read). 16 row-groups x 32 col-pairs.
        const int cp2 = tid & 31;
        const int rg = tid >> 5;              // 0..15, 16 rows each
        const int lc = cp2 * 2;
        const int gcol = bid * 64 + lc;
        const float ma0 = s_mu[lc],       ma1 = s_mu[lc + 1];
        const float wa0 = s_inv[lc],      wa1 = s_inv[lc + 1];
        const float mb0 = s_mu[64 + lc],  mb1 = s_mu[64 + lc + 1];
        const float wb0 = s_inv[64 + lc], wb1 = s_inv[64 + lc + 1];
        const float* __restrict__ qa = za + (size_t)(rg * 16) * D_COLS + gcol;
        const float* __restrict__ qb = zb + (size_t)(rg * 16) * D_COLS + gcol;
        __nv_bfloat16* __restrict__ oa = g_Zn[0] + (size_t)(rg * 16) * D_COLS + gcol;
        __nv_bfloat16* __restrict__ ob = g_Zn[1] + (size_t)(rg * 16) * D_COLS + gcol;
#pragma unroll 4
        for (int n = 0; n < 16; ++n) {
            float2 va = *(const float2*)&qa[n * D_COLS];
            float2 vb = *(const float2*)&qb[n * D_COLS];
            *(__nv_bfloat162*)&oa[n * D_COLS] =
                __floats2bfloat162_rn((va.x - ma0) * wa0, (va.y - ma1) * wa1);
            *(__nv_bfloat162*)&ob[n * D_COLS] =
                __floats2bfloat162_rn((vb.x - mb0) * wb0, (vb.y - mb1) * wb1);
        }
    }

    grid_sync();

    // ========== Phase 1 (bid<144): 3-stage pipelined tensor-core Gram =======
    // 16 warps, 4x4 warp grid, 32x32 warp tiles, BK=64, 1 barrier per iter.
    if (bid < 2 * NTILES * SPLITS) {
        const int sel = bid / (NTILES * SPLITS);
        const int rem = bid % (NTILES * SPLITS);
        const int pair = rem / SPLITS;
        const int s = rem % SPLITS;
        const bool dup = (pair != 1);      // diagonal tile pairs: B tile == A tile

        const int m0 = (pair == 2) ? 128 : 0;
        const int n0 = (pair == 0) ? 0 : 128;
        // 128 k-chunks of 64: splits 0..15 get 5, 16..23 get 6
        const int ks = (s < 16) ? s * 5 : 80 + (s - 16) * 6;
        const int kn = (s < 16) ? 5 : 6;

        const __nv_bfloat16* __restrict__ gA = g_Zn[sel] + (size_t)m0 * D_COLS;
        const __nv_bfloat16* __restrict__ gB = g_Zn[sel] + (size_t)n0 * D_COLS;

        const int warp = tid >> 5;
        const int lane = tid & 31;
        const int wm = warp & 3;    // 4 m-strips of 32
        const int wn = warp >> 2;   // 4 n-strips of 32

        float acc[2][4][4];
#pragma unroll
        for (int i = 0; i < 2; ++i)
#pragma unroll
            for (int j = 0; j < 4; ++j)
#pragma unroll
                for (int k = 0; k < 4; ++k) acc[i][j][k] = 0.f;

        const unsigned sBase = (unsigned)__cvta_generic_to_shared(dyn);
        const unsigned bRegion = dup ? sBase : (sBase + (unsigned)A_REGION);
        const int laR = (lane & 7) + (lane & 8);
        const int laC = (lane >> 1) & 8;
        const int lbR = (lane & 7) + ((lane >> 1) & 8);
        const int lbC = (lane & 8);
        const unsigned aAddr = sBase + (unsigned)(((wm * 32 + laR) * LDB + laC) * 2);
        const unsigned bAddr = bRegion + (unsigned)(((wn * 32 + lbR) * LDB + lbC) * 2);

        // stage one 128x64 bf16 tile per side: 1024 16B chunks -> 2 per thread
#define STAGE(slot, kidx)                                                         \
        {                                                                         \
            const int k0_ = (ks + (kidx)) * BK;                                   \
            const unsigned so_ = (unsigned)(slot) * TILE_BUF;                     \
            _Pragma("unroll")                                                     \
            for (int i_ = 0; i_ < 2; ++i_) {                                      \
                const int l_ = i_ * NTHR + tid;                                   \
                const int r_ = l_ >> 3;                                           \
                const int c_ = l_ & 7;                                            \
                cp_async16(sBase + so_ + (unsigned)(r_ * 144 + c_ * 16),          \
                           gA + (size_t)r_ * D_COLS + k0_ + c_ * 8);              \
                if (!dup)                                                         \
                    cp_async16(sBase + (unsigned)A_REGION + so_ + (unsigned)(r_ * 144 + c_ * 16), \
                               gB + (size_t)r_ * D_COLS + k0_ + c_ * 8);          \
            }                                                                     \
            asm volatile("cp.async.commit_group;\n");                             \
        }

        STAGE(0, 0);
        STAGE(1, 1);
        for (int it = 0; it < kn; ++it) {
            if (it == kn - 1) { asm volatile("cp.async.wait_group 0;\n"); }
            else              { asm volatile("cp.async.wait_group 1;\n"); }
            __syncthreads();   // single barrier per iter: orders prev reads + this chunk's data
            if (it + 2 < kn) STAGE((it + 2) % NSTAGE, it + 2);

            const unsigned off = (unsigned)((it % NSTAGE) * TILE_BUF);
#pragma unroll
            for (int kf = 0; kf < 4; ++kf) {
                unsigned A0[4], A1[4];
                ldm4(A0, aAddr + off + (unsigned)(kf * 32));
                ldm4(A1, aAddr + off + (unsigned)(16 * LDB * 2 + kf * 32));
#pragma unroll
                for (int fp = 0; fp < 2; ++fp) {
                    unsigned B[4];
                    ldm4(B, bAddr + off + (unsigned)(fp * 16 * LDB * 2 + kf * 32));
                    mma_bf16(acc[0][2 * fp],     A0, B[0], B[1]);
                    mma_bf16(acc[0][2 * fp + 1], A0, B[2], B[3]);
                    mma_bf16(acc[1][2 * fp],     A1, B[0], B[1]);
                    mma_bf16(acc[1][2 * fp + 1], A1, B[2], B[3]);
                }
            }
        }
#undef STAGE

        float* __restrict__ outp = &g_GP[sel][s][pair * TILE_ELEMS];
#pragma unroll
        for (int fm = 0; fm < 2; ++fm)
#pragma unroll
            for (int fn = 0; fn < 4; ++fn) {
                const int i = wm * 32 + fm * 16 + (lane >> 2);
                const int j = wn * 32 + fn * 8 + (lane & 3) * 2;
                float2 lo = {acc[fm][fn][0], acc[fm][fn][1]};
                float2 hi = {acc[fm][fn][2], acc[fm][fn][3]};
                *(float2*)&outp[i * 128 + j] = lo;
                *(float2*)&outp[(i + 8) * 128 + j] = hi;
            }
    }

    grid_sync();

    // ========== Phase 2: cross reduction (all 148 blocks) + fused final =====
    {
        float v = 0.f;
        const int t = bid * TPB_CROSS + tid;   // 84 contiguous float4 tasks/block
        if (tid < TPB_CROSS && t < CROSS_TASKS) {
            const int pair = t >> 12;
            const float w = (pair == 1) ? 2.f : 1.f;
            float4 ga = {0.f, 0.f, 0.f, 0.f}, gb = {0.f, 0.f, 0.f, 0.f};
#pragma unroll
            for (int s = 0; s < SPLITS; ++s) {
                const float4 a = *(const float4*)&g_GP[0][s][t * 4];
                const float4 bb = *(const float4*)&g_GP[1][s][t * 4];
                ga.x += a.x; ga.y += a.y; ga.z += a.z; ga.w += a.w;
                gb.x += bb.x; gb.y += bb.y; gb.z += bb.z; gb.w += bb.w;
            }
            v = w * (ga.x * gb.x + ga.y * gb.y + ga.z * gb.z + ga.w * gb.w);
        }
        __syncthreads();
        s_red[tid] = v;
        __syncthreads();
#pragma unroll
        for (int off = 64; off > 0; off >>= 1) {   // data only in tids 0..83 (<128)
            if (tid < off) s_red[tid] += s_red[tid + off];
            __syncthreads();
        }
        if (tid == 0) {
            g_red[bid] = s_red[0];
            __threadfence();
            s_last = (atomicAdd(&g_fin, 1u) == NBLK - 1) ? 1u : 0u;
        }
        __syncthreads();

        if (s_last) {
            __threadfence();
            float v2 = 0.f;
            if (tid < NBLK) v2 = (*(volatile float*)&g_red[tid]) * (LAMBDA / (256.f * 256.f));
            if (tid < 128) v2 += *(volatile float*)&g_diag[tid];
            s_red[tid] = v2;
            __syncthreads();
#pragma unroll
            for (int off = 128; off > 0; off >>= 1) {   // data in tids 0..147 (<256)
                if (tid < off) s_red[tid] += s_red[tid + off];
                __syncthreads();
            }
            if (tid == 0) {
                out[0] = s_red[0];
                g_fin = 0;   // reset for next graph replay
            }
        }
    }
}

// ---------------------------------------------------------------------------
extern "C" void kernel_launch(void* const* d_in, const int* in_sizes, int n_in,
                              void* d_out, int out_size) {
    const float* za = (const float*)d_in[0];
    const float* zb = (const float*)d_in[1];
    float* out = (float*)d_out;
    cudaFuncSetAttribute(fused_kernel, cudaFuncAttributeMaxDynamicSharedMemorySize, DYN_SMEM);
    fused_kernel<<<NBLK, NTHR, DYN_SMEM>>>(za, zb, out);
}